// round 1
// baseline (speedup 1.0000x reference)
#include <cuda_runtime.h>
#include <cstdint>

#define BB 64
#define TT 1024
#define EE 300
#define HH 512
#define G4 2048
#define M_ROWS (BB*TT)

// ---------------- scratch (device globals; no allocations) ----------------
__device__ float g_out1[(size_t)M_ROWS * EE];     // 78.6 MB embeddings
__device__ float g_zx[(size_t)M_ROWS * G4];       // 512 MB  zx = out1@Wx + b
__device__ float g_h[2][BB * HH];                 // double-buffered hidden state
__device__ float g_c1[BB * 8 * 256];              // conv1 window t=6..13
__device__ float g_c2[BB * HH];                   // conv2 at t=9
__device__ unsigned g_arrive;                     // grid barrier counter

// ---------------- init: h0 -> buffer 0, reset barrier ----------------
__global__ void init_kernel(const float* __restrict__ h0) {
    int i = blockIdx.x * blockDim.x + threadIdx.x;
    if (i < BB * HH) g_h[0][i] = h0[i];
    if (i == 0) g_arrive = 0u;
}

// ---------------- embedding gather ----------------
__global__ void embed_kernel(const int* __restrict__ idx, const float* __restrict__ table) {
    long gid = (long)blockIdx.x * blockDim.x + threadIdx.x;
    const long total = (long)M_ROWS * 75;          // 300 floats = 75 float4 per row
    if (gid >= total) return;
    long r = gid / 75;
    int  e4 = (int)(gid % 75);
    int row = idx[r];
    ((float4*)g_out1)[r * 75 + e4] = ((const float4*)table)[(long)row * 75 + e4];
}

// ---------------- zx GEMM: [65536,300] @ [300,2048] + bias ----------------
#define GBM 128
#define GBN 128
#define GBK 12   // 300 = 25 * 12
__global__ __launch_bounds__(256) void zx_gemm_kernel(const float* __restrict__ Wx,
                                                      const float* __restrict__ bias) {
    __shared__ float As[GBK][GBM];
    __shared__ float Bs[GBK][GBN];
    const int bm = blockIdx.y * GBM;
    const int bn = blockIdx.x * GBN;
    const int tid = threadIdx.x;
    const int tm = (tid >> 4) * 8;
    const int tn = (tid & 15) * 8;
    float acc[8][8];
#pragma unroll
    for (int i = 0; i < 8; i++)
#pragma unroll
        for (int j = 0; j < 8; j++) acc[i][j] = 0.f;

    for (int k0 = 0; k0 < EE; k0 += GBK) {
#pragma unroll
        for (int i = 0; i < 6; i++) {                  // 128*12 = 1536 elems
            int idx = tid + i * 256;
            int m = idx / GBK, k = idx % GBK;
            As[k][m] = g_out1[(long)(bm + m) * EE + k0 + k];
        }
#pragma unroll
        for (int i = 0; i < 6; i++) {                  // 12*128 = 1536 elems
            int idx = tid + i * 256;
            int k = idx >> 7, n = idx & 127;
            Bs[k][n] = Wx[(long)(k0 + k) * G4 + bn + n];
        }
        __syncthreads();
#pragma unroll
        for (int k = 0; k < GBK; k++) {
            float4 a0 = *(const float4*)&As[k][tm];
            float4 a1 = *(const float4*)&As[k][tm + 4];
            float4 b0 = *(const float4*)&Bs[k][tn];
            float4 b1 = *(const float4*)&Bs[k][tn + 4];
            float ra[8] = {a0.x, a0.y, a0.z, a0.w, a1.x, a1.y, a1.z, a1.w};
            float rb[8] = {b0.x, b0.y, b0.z, b0.w, b1.x, b1.y, b1.z, b1.w};
#pragma unroll
            for (int i = 0; i < 8; i++)
#pragma unroll
                for (int j = 0; j < 8; j++) acc[i][j] += ra[i] * rb[j];
        }
        __syncthreads();
    }
#pragma unroll
    for (int i = 0; i < 8; i++)
#pragma unroll
        for (int j = 0; j < 8; j++)
            g_zx[(long)(bm + tm + i) * G4 + bn + tn + j] = acc[i][j] + bias[bn + tn + j];
}

// ---------------- conv1, only t in [6,13] (inputs t in [2,18], interior) ----------------
__global__ __launch_bounds__(256) void conv1_kernel(const float* __restrict__ W1,
                                                    const float* __restrict__ b1) {
    int bb = blockIdx.x >> 1;
    int th = blockIdx.x & 1;        // t-half: outputs t = 6+th*4 .. 6+th*4+3
    __shared__ float xs[19][EE];
    int tid = threadIdx.x;
    for (int i = tid; i < 19 * EE; i += 256) {
        int rt = i / EE, e = i % EE;
        xs[rt][e] = g_out1[((long)(bb * TT) + 2 + rt) * EE + e];
    }
    __syncthreads();
    int m = tid;                    // 0..255 output channel
    float acc[4] = {0.f, 0.f, 0.f, 0.f};
    for (int w = 0; w < 10; w++) {
        for (int e = 0; e < EE; e++) {
            float wv = W1[((w * EE) + e) * 256 + m];
#pragma unroll
            for (int q = 0; q < 4; q++) acc[q] += xs[th * 4 + q + w][e] * wv;
        }
    }
    float bm = b1[m];
#pragma unroll
    for (int q = 0; q < 4; q++) {
        float v = acc[q] + bm;
        v = v > 0.f ? v : 0.f;
        g_c1[(bb * 8 + th * 4 + q) * 256 + m] = v;
    }
}

// ---------------- conv2 at t=9 (inputs conv1 t in [6,13]) ----------------
__global__ __launch_bounds__(512) void conv2_kernel(const float* __restrict__ W2,
                                                    const float* __restrict__ b2) {
    int bb = blockIdx.x;
    __shared__ float cs[8 * 256];
    int tid = threadIdx.x;
    for (int i = tid; i < 2048; i += 512) cs[i] = g_c1[bb * 2048 + i];
    __syncthreads();
    int n = tid;
    float acc = 0.f;
    for (int i = 0; i < 2048; i++)
        acc += cs[i] * W2[(long)i * HH + n];
    float v = acc + b2[n];
    v = v > 0.f ? v : 0.f;
    g_c2[bb * HH + n] = v;
}

// ---------------- persistent masked LSTM ----------------
#define LC 128            // CTAs; each owns 4 h-columns
#define HS_STRIDE 516     // padded h row (conflict-free LDS.128 with b = i*16+bg)

__device__ __forceinline__ float sigf(float x) { return 1.f / (1.f + __expf(-x)); }

__global__ __launch_bounds__(256, 1) void lstm_kernel(const float* __restrict__ Wh,
                                                      const float* __restrict__ c0,
                                                      const int* __restrict__ in_seq,
                                                      float* __restrict__ out_enc,
                                                      float* __restrict__ out_res9,
                                                      float* __restrict__ out_c) {
    extern __shared__ float smem[];
    float* hs  = smem;                       // 64 * 516
    float* whs = hs + 64 * HS_STRIDE;        // 16 * 512  (layout [g*4+jj][k])
    float* red = whs + 16 * 512;             // 3 * 64 * 16

    const int tid = threadIdx.x;
    const int bg = tid & 15;                 // batch group 0..15
    const int jj = (tid >> 4) & 3;           // local h-column 0..3
    const int ks = tid >> 6;                 // k-split 0..3
    const int j0 = blockIdx.x * 4;

    // load Wh slice once: 16 cols x 512
    for (int i = tid; i < 16 * 512; i += 256) {
        int lc = i >> 9;
        int k  = i & 511;
        int g = lc >> 2, j = lc & 3;
        whs[lc * 512 + k] = Wh[(long)k * G4 + j0 + j + g * 512];
    }

    float creg[4];
#pragma unroll
    for (int i = 0; i < 4; i++) {
        int b = i * 16 + bg;
        creg[i] = c0[b * HH + j0 + jj];
    }
    __syncthreads();

    for (int t = 0; t < TT; t++) {
        const float* hsrc = g_h[t & 1];
        float* hdst = g_h[(t & 1) ^ 1];

        // broadcast-load h into smem (bypass L1: other CTAs wrote it)
        for (int i = tid; i < (BB * HH) / 4; i += 256) {
            int b = i >> 7;
            int kq = i & 127;
            float4 v = __ldcg(((const float4*)hsrc) + i);
            *(float4*)&hs[b * HS_STRIDE + kq * 4] = v;
        }
        __syncthreads();

        float acc[4][4];
#pragma unroll
        for (int i = 0; i < 4; i++)
#pragma unroll
            for (int g = 0; g < 4; g++) acc[i][g] = 0.f;

        const int kbase = ks * 128;
#pragma unroll 4
        for (int kk = 0; kk < 128; kk += 4) {
            int k = kbase + kk;
            float4 wv[4], hv[4];
#pragma unroll
            for (int g = 0; g < 4; g++) wv[g] = *(const float4*)&whs[(g * 4 + jj) * 512 + k];
#pragma unroll
            for (int i = 0; i < 4; i++) hv[i] = *(const float4*)&hs[(i * 16 + bg) * HS_STRIDE + k];
#pragma unroll
            for (int i = 0; i < 4; i++)
#pragma unroll
                for (int g = 0; g < 4; g++)
                    acc[i][g] += hv[i].x * wv[g].x + hv[i].y * wv[g].y
                               + hv[i].z * wv[g].z + hv[i].w * wv[g].w;
        }

        if (ks > 0) {
            float* rp = &red[((ks - 1) * 64 + jj * 16 + bg) * 16];
#pragma unroll
            for (int i = 0; i < 4; i++)
#pragma unroll
                for (int g = 0; g < 4; g++) rp[i * 4 + g] = acc[i][g];
        }
        __syncthreads();

        if (ks == 0) {
#pragma unroll
            for (int r = 0; r < 3; r++) {
                float* rp = &red[(r * 64 + jj * 16 + bg) * 16];
#pragma unroll
                for (int i = 0; i < 4; i++)
#pragma unroll
                    for (int g = 0; g < 4; g++) acc[i][g] += rp[i * 4 + g];
            }
            const int col = j0 + jj;
#pragma unroll
            for (int i = 0; i < 4; i++) {
                int b = i * 16 + bg;
                long zb = ((long)b * TT + t) * G4;
                float zi = acc[i][0] + __ldcg(&g_zx[zb + col]);
                float zf = acc[i][1] + __ldcg(&g_zx[zb + col + 512]);
                float zg = acc[i][2] + __ldcg(&g_zx[zb + col + 1024]);
                float zo = acc[i][3] + __ldcg(&g_zx[zb + col + 1536]);
                float cn = sigf(zf) * creg[i] + sigf(zi) * tanhf(zg);
                float hn = sigf(zo) * tanhf(cn);
                if (in_seq[b * TT + t] == 0) {           // masked: carry state
                    hn = hs[(i * 16 + bg) * HS_STRIDE + col];
                    cn = creg[i];
                }
                creg[i] = cn;
                __stcg(&hdst[b * HH + col], hn);
                out_enc[((long)b * TT + t) * HH + col] = hn;
                if (t == 9)       out_res9[b * HH + col] = hn + g_c2[b * HH + col];
                if (t == TT - 1)  out_c[b * HH + col] = cn;
            }
        }

        // ---- grid barrier (monotonic counter; reset by init kernel) ----
        __syncthreads();
        __threadfence();
        if (tid == 0) {
            atomicAdd(&g_arrive, 1u);
            unsigned target = (unsigned)gridDim.x * (unsigned)(t + 1);
            while (*((volatile unsigned*)&g_arrive) < target) { }
        }
        __syncthreads();
    }
}

// ---------------- launch ----------------
extern "C" void kernel_launch(void* const* d_in, const int* in_sizes, int n_in,
                              void* d_out, int out_size) {
    const int*   in_seq = (const int*)  d_in[0];
    const float* h0     = (const float*)d_in[1];
    const float* c0     = (const float*)d_in[2];
    const float* table  = (const float*)d_in[3];
    const float* W1     = (const float*)d_in[4];
    const float* b1     = (const float*)d_in[5];
    const float* W2     = (const float*)d_in[6];
    const float* b2     = (const float*)d_in[7];
    const float* Wx     = (const float*)d_in[8];
    const float* Wh     = (const float*)d_in[9];
    const float* bias   = (const float*)d_in[10];

    float* out      = (float*)d_out;
    float* out_enc  = out;                                  // [B,T,H]
    float* out_res9 = out + (size_t)BB * TT * HH;           // [B,H]
    float* out_c    = out_res9 + BB * HH;                   // [B,H]

    const int lstm_smem = (64 * HS_STRIDE + 16 * 512 + 3 * 64 * 16) * 4;  // 177152 B
    cudaFuncSetAttribute(lstm_kernel, cudaFuncAttributeMaxDynamicSharedMemorySize, lstm_smem);

    init_kernel<<<(BB * HH + 255) / 256, 256>>>(h0);
    embed_kernel<<<((long)M_ROWS * 75 + 255) / 256, 256>>>(in_seq, table);
    dim3 gg(G4 / GBN, M_ROWS / GBM);   // (16, 512)
    zx_gemm_kernel<<<gg, 256>>>(Wx, bias);
    conv1_kernel<<<BB * 2, 256>>>(W1, b1);
    conv2_kernel<<<BB, 512>>>(W2, b2);
    lstm_kernel<<<LC, 256, lstm_smem>>>(Wh, c0, in_seq, out_enc, out_res9, out_c);
}

// round 2
// speedup vs baseline: 1.8949x; 1.8949x over previous
#include <cuda_runtime.h>
#include <cstdint>

#define BB 64
#define TT 1024
#define EE 300
#define HH 512
#define G4 2048
#define M_ROWS (BB*TT)

// ---------------- scratch (device globals; no allocations) ----------------
__device__ float g_out1[(size_t)M_ROWS * EE];     // 78.6 MB embeddings
__device__ float g_zx[(size_t)M_ROWS * G4];       // 512 MB  zx = out1@Wx + b
__device__ float g_h[2][BB * HH];                 // double-buffered hidden state
__device__ float g_c1[BB * 8 * 256];              // conv1 window t=6..13
__device__ float g_c2[BB * HH];                   // conv2 at t=9
__device__ unsigned g_arrive;                     // grid barrier counter

// ---------------- packed f32x2 helpers (FFMA2: 2x fp32 throughput) --------
__device__ __forceinline__ uint64_t pack2(float lo, float hi) {
    uint64_t r; asm("mov.b64 %0, {%1, %2};" : "=l"(r) : "f"(lo), "f"(hi)); return r;
}
__device__ __forceinline__ void fma2(uint64_t& d, uint64_t a, uint64_t b) {
    asm("fma.rn.f32x2 %0, %1, %2, %0;" : "+l"(d) : "l"(a), "l"(b));
}
__device__ __forceinline__ void unpack2(uint64_t v, float& lo, float& hi) {
    asm("mov.b64 {%0, %1}, %2;" : "=f"(lo), "=f"(hi) : "l"(v));
}

// ---------------- init: h0 -> buffer 0, reset barrier ----------------
__global__ void init_kernel(const float* __restrict__ h0) {
    int i = blockIdx.x * blockDim.x + threadIdx.x;
    if (i < BB * HH) g_h[0][i] = h0[i];
    if (i == 0) g_arrive = 0u;
}

// ---------------- embedding gather ----------------
__global__ void embed_kernel(const int* __restrict__ idx, const float* __restrict__ table) {
    long gid = (long)blockIdx.x * blockDim.x + threadIdx.x;
    const long total = (long)M_ROWS * 75;          // 300 floats = 75 float4 per row
    if (gid >= total) return;
    long r = gid / 75;
    int  e4 = (int)(gid % 75);
    int row = idx[r];
    ((float4*)g_out1)[r * 75 + e4] = ((const float4*)table)[(long)row * 75 + e4];
}

// ---------------- zx GEMM: [65536,300] @ [300,2048] + bias ----------------
#define GBM 128
#define GBN 128
#define GBK 12   // 300 = 25 * 12
__global__ __launch_bounds__(256) void zx_gemm_kernel(const float* __restrict__ Wx,
                                                      const float* __restrict__ bias) {
    __shared__ float As[GBK][GBM];
    __shared__ float Bs[GBK][GBN];
    const int bm = blockIdx.y * GBM;
    const int bn = blockIdx.x * GBN;
    const int tid = threadIdx.x;
    const int tm = (tid >> 4) * 8;
    const int tn = (tid & 15) * 8;

    uint64_t accp[8][4];   // 8 rows x 4 packed col-pairs
#pragma unroll
    for (int i = 0; i < 8; i++)
#pragma unroll
        for (int p = 0; p < 4; p++) accp[i][p] = 0ull;

    for (int k0 = 0; k0 < EE; k0 += GBK) {
#pragma unroll
        for (int i = 0; i < 6; i++) {                  // 128*12 = 1536 elems
            int idx = tid + i * 256;
            int m = idx / GBK, k = idx % GBK;
            As[k][m] = g_out1[(long)(bm + m) * EE + k0 + k];
        }
#pragma unroll
        for (int i = 0; i < 6; i++) {                  // 12*128 = 1536 elems
            int idx = tid + i * 256;
            int k = idx >> 7, n = idx & 127;
            Bs[k][n] = Wx[(long)(k0 + k) * G4 + bn + n];
        }
        __syncthreads();
#pragma unroll
        for (int k = 0; k < GBK; k++) {
            float4 a0 = *(const float4*)&As[k][tm];
            float4 a1 = *(const float4*)&As[k][tm + 4];
            float4 b0 = *(const float4*)&Bs[k][tn];
            float4 b1 = *(const float4*)&Bs[k][tn + 4];
            uint64_t bp[4] = {pack2(b0.x, b0.y), pack2(b0.z, b0.w),
                              pack2(b1.x, b1.y), pack2(b1.z, b1.w)};
            float ra[8] = {a0.x, a0.y, a0.z, a0.w, a1.x, a1.y, a1.z, a1.w};
#pragma unroll
            for (int i = 0; i < 8; i++) {
                uint64_t ap = pack2(ra[i], ra[i]);
#pragma unroll
                for (int p = 0; p < 4; p++) fma2(accp[i][p], ap, bp[p]);
            }
        }
        __syncthreads();
    }

    float bj[8];
#pragma unroll
    for (int j = 0; j < 8; j++) bj[j] = bias[bn + tn + j];
#pragma unroll
    for (int i = 0; i < 8; i++) {
        float c[8];
#pragma unroll
        for (int p = 0; p < 4; p++) unpack2(accp[i][p], c[2 * p], c[2 * p + 1]);
        float4 v0 = make_float4(c[0] + bj[0], c[1] + bj[1], c[2] + bj[2], c[3] + bj[3]);
        float4 v1 = make_float4(c[4] + bj[4], c[5] + bj[5], c[6] + bj[6], c[7] + bj[7]);
        float* dst = &g_zx[(long)(bm + tm + i) * G4 + bn + tn];
        *(float4*)dst = v0;
        *(float4*)(dst + 4) = v1;
    }
}

// ---------------- conv1, only t in [6,13] (inputs t in [2,18], interior) ----------------
__global__ __launch_bounds__(256) void conv1_kernel(const float* __restrict__ W1,
                                                    const float* __restrict__ b1) {
    int bb = blockIdx.x >> 1;
    int th = blockIdx.x & 1;        // t-half: outputs t = 6+th*4 .. 6+th*4+3
    __shared__ float xs[19][EE];
    int tid = threadIdx.x;
    for (int i = tid; i < 19 * EE; i += 256) {
        int rt = i / EE, e = i % EE;
        xs[rt][e] = g_out1[((long)(bb * TT) + 2 + rt) * EE + e];
    }
    __syncthreads();
    int m = tid;                    // 0..255 output channel
    float acc[4] = {0.f, 0.f, 0.f, 0.f};
    for (int w = 0; w < 10; w++) {
#pragma unroll 4
        for (int e = 0; e < EE; e++) {
            float wv = __ldg(&W1[((w * EE) + e) * 256 + m]);
#pragma unroll
            for (int q = 0; q < 4; q++) acc[q] += xs[th * 4 + q + w][e] * wv;
        }
    }
    float bm = b1[m];
#pragma unroll
    for (int q = 0; q < 4; q++) {
        float v = acc[q] + bm;
        v = v > 0.f ? v : 0.f;
        g_c1[(bb * 8 + th * 4 + q) * 256 + m] = v;
    }
}

// ---------------- conv2 at t=9 (inputs conv1 t in [6,13]) ----------------
__global__ __launch_bounds__(512) void conv2_kernel(const float* __restrict__ W2,
                                                    const float* __restrict__ b2) {
    int bb = blockIdx.x;
    __shared__ float cs[8 * 256];
    int tid = threadIdx.x;
    for (int i = tid; i < 2048; i += 512) cs[i] = g_c1[bb * 2048 + i];
    __syncthreads();
    int n = tid;
    float acc = 0.f;
#pragma unroll 8
    for (int i = 0; i < 2048; i++)
        acc += cs[i] * __ldg(&W2[(long)i * HH + n]);
    float v = acc + b2[n];
    v = v > 0.f ? v : 0.f;
    g_c2[bb * HH + n] = v;
}

// ---------------- persistent masked LSTM ----------------
#define LC 128            // CTAs; each owns 4 h-columns
#define HS_STRIDE 516     // padded h row

__device__ __forceinline__ float sigf(float x) { return 1.f / (1.f + __expf(-x)); }

__global__ __launch_bounds__(256, 1) void lstm_kernel(const float* __restrict__ Wh,
                                                      const float* __restrict__ c0,
                                                      const int* __restrict__ in_seq,
                                                      float* __restrict__ out_enc,
                                                      float* __restrict__ out_res9,
                                                      float* __restrict__ out_c) {
    extern __shared__ float smem[];
    float* hs     = smem;                          // 64 * 516          = 33024
    float* whs    = hs + 64 * HS_STRIDE;           // [jj][k][g] 16*512*... = 8192
    float* red    = whs + 8192;                    // [ks*4+g][jj][b] 4*4*4*64 = 4096
    float* hstage = red + 4096;                    // [b][jc] 256

    const int tid = threadIdx.x;
    // accumulate-phase identity
    const int bg = tid & 15;                 // batch group 0..15
    const int jj = (tid >> 4) & 3;           // local h-column 0..3
    const int ks = tid >> 6;                 // k-split 0..3
    // gate-phase identity: one (b, col) per thread
    const int b  = tid & 63;
    const int jc = tid >> 6;
    const int j0 = blockIdx.x * 4;
    const int col = j0 + jc;

    // Wh slice, gate-interleaved: whs[(jj*512+k)*4 + g] = Wh[k][j0+jj + g*512]
    for (int f = tid; f < 16 * 512; f += 256) {
        int wjj = f >> 11;
        int k   = (f >> 2) & 511;
        int g   = f & 3;
        whs[f] = Wh[(long)k * G4 + j0 + wjj + g * 512];
    }

    float creg = c0[b * HH + col];
    __syncthreads();

    for (int t = 0; t < TT; t++) {
        const float* hsrc = g_h[t & 1];
        float* hdst = g_h[(t & 1) ^ 1];

        // phase A: prefetch zx + mask for this thread's (b, col) -- constant data
        const size_t zb = ((size_t)b * TT + t) * G4 + col;
        float zr0 = __ldg(&g_zx[zb]);
        float zr1 = __ldg(&g_zx[zb + 512]);
        float zr2 = __ldg(&g_zx[zb + 1024]);
        float zr3 = __ldg(&g_zx[zb + 1536]);
        int   mreg = in_seq[b * TT + t];

        // phase B: broadcast-load h into smem (L2; other CTAs wrote it)
        for (int i = tid; i < (BB * HH) / 4; i += 256) {
            int bb2 = i >> 7;
            int kq  = i & 127;
            float4 v = __ldcg(((const float4*)hsrc) + i);
            *(float4*)&hs[bb2 * HS_STRIDE + kq * 4] = v;
        }
        __syncthreads();

        // phase C: packed-f32x2 MMA, k-split by 4
        uint64_t accp[4][2];
#pragma unroll
        for (int i = 0; i < 4; i++) { accp[i][0] = 0ull; accp[i][1] = 0ull; }

        const int kbase = ks * 128;
#pragma unroll 4
        for (int kk = 0; kk < 128; kk += 4) {
            const int k = kbase + kk;
            float4 hv[4];
#pragma unroll
            for (int i = 0; i < 4; i++)
                hv[i] = *(const float4*)&hs[(i * 16 + bg) * HS_STRIDE + k];
            const ulonglong2* wv2 = (const ulonglong2*)&whs[(jj * 512 + k) * 4];
#pragma unroll
            for (int q = 0; q < 4; q++) {
                ulonglong2 w = wv2[q];
#pragma unroll
                for (int i = 0; i < 4; i++) {
                    float hvq = ((const float*)&hv[i])[q];
                    uint64_t hb = pack2(hvq, hvq);
                    fma2(accp[i][0], hb, w.x);
                    fma2(accp[i][1], hb, w.y);
                }
            }
        }

        // all k-splits write partials
#pragma unroll
        for (int i = 0; i < 4; i++) {
#pragma unroll
            for (int p = 0; p < 2; p++) {
                float v0, v1;
                unpack2(accp[i][p], v0, v1);
                int g = 2 * p;
                red[((ks * 4 + g) * 4 + jj) * 64 + i * 16 + bg] = v0;
                red[((ks * 4 + g + 1) * 4 + jj) * 64 + i * 16 + bg] = v1;
            }
        }
        __syncthreads();

        // phase D: one (b, col) output per thread
        {
            float z0 = zr0, z1 = zr1, z2 = zr2, z3 = zr3;
#pragma unroll
            for (int r = 0; r < 4; r++) {
                z0 += red[((r * 4 + 0) * 4 + jc) * 64 + b];
                z1 += red[((r * 4 + 1) * 4 + jc) * 64 + b];
                z2 += red[((r * 4 + 2) * 4 + jc) * 64 + b];
                z3 += red[((r * 4 + 3) * 4 + jc) * 64 + b];
            }
            float cn = sigf(z1) * creg + sigf(z0) * tanhf(z2);
            float hn = sigf(z3) * tanhf(cn);
            if (mreg == 0) {                     // masked: carry state
                hn = hs[b * HS_STRIDE + col];
                cn = creg;
            }
            creg = cn;
            hstage[b * 4 + jc] = hn;
            if (t == 9)      out_res9[b * HH + col] = hn + g_c2[b * HH + col];
            if (t == TT - 1) out_c[b * HH + col] = cn;
        }
        __syncthreads();

        // phase E: coalesced float4 stores of new h + out_enc
        if (tid < 64) {
            float4 hv4 = *(const float4*)&hstage[tid * 4];
            __stcg((float4*)&hdst[tid * HH + j0], hv4);
            *(float4*)&out_enc[((size_t)tid * TT + t) * HH + j0] = hv4;
        }

        // ---- grid barrier (monotonic counter; reset by init kernel) ----
        __threadfence();
        __syncthreads();
        if (tid == 0) {
            atomicAdd(&g_arrive, 1u);
            unsigned target = (unsigned)gridDim.x * (unsigned)(t + 1);
            while (*((volatile unsigned*)&g_arrive) < target) { }
        }
        __syncthreads();
    }
}

// ---------------- launch ----------------
extern "C" void kernel_launch(void* const* d_in, const int* in_sizes, int n_in,
                              void* d_out, int out_size) {
    const int*   in_seq = (const int*)  d_in[0];
    const float* h0     = (const float*)d_in[1];
    const float* c0     = (const float*)d_in[2];
    const float* table  = (const float*)d_in[3];
    const float* W1     = (const float*)d_in[4];
    const float* b1     = (const float*)d_in[5];
    const float* W2     = (const float*)d_in[6];
    const float* b2     = (const float*)d_in[7];
    const float* Wx     = (const float*)d_in[8];
    const float* Wh     = (const float*)d_in[9];
    const float* bias   = (const float*)d_in[10];

    float* out      = (float*)d_out;
    float* out_enc  = out;                                  // [B,T,H]
    float* out_res9 = out + (size_t)BB * TT * HH;           // [B,H]
    float* out_c    = out_res9 + BB * HH;                   // [B,H]

    const int lstm_smem = (64 * HS_STRIDE + 8192 + 4096 + 256) * 4;  // 182272 B
    cudaFuncSetAttribute(lstm_kernel, cudaFuncAttributeMaxDynamicSharedMemorySize, lstm_smem);

    init_kernel<<<(BB * HH + 255) / 256, 256>>>(h0);
    embed_kernel<<<(int)(((long)M_ROWS * 75 + 255) / 256), 256>>>(in_seq, table);
    dim3 gg(G4 / GBN, M_ROWS / GBM);   // (16, 512)
    zx_gemm_kernel<<<gg, 256>>>(Wx, bias);
    conv1_kernel<<<BB * 2, 256>>>(W1, b1);
    conv2_kernel<<<BB, 512>>>(W2, b2);
    lstm_kernel<<<LC, 256, lstm_smem>>>(Wh, c0, in_seq, out_enc, out_res9, out_c);
}

// round 6
// speedup vs baseline: 2.1545x; 1.1370x over previous
#include <cuda_runtime.h>
#include <cstdint>

#define BB 64
#define TT 1024
#define EE 300
#define HH 512
#define G4 2048
#define M_ROWS (BB*TT)

// ---------------- scratch (device globals; no allocations) ----------------
__device__ float g_out1[(size_t)M_ROWS * EE];     // 78.6 MB embeddings
__device__ float g_zx[(size_t)M_ROWS * G4];       // 512 MB  zx = out1@Wx + b
__device__ float g_h[2][BB * HH];                 // double-buffered hidden state
__device__ float g_c1[BB * 8 * 256];              // conv1 window t=6..13
__device__ float g_c2[BB * HH];                   // conv2 at t=9
__device__ unsigned g_arrive;                     // grid barrier counter

// ---------------- packed f32x2 helpers ----------------
__device__ __forceinline__ uint64_t pack2(float lo, float hi) {
    uint64_t r; asm("mov.b64 %0, {%1, %2};" : "=l"(r) : "f"(lo), "f"(hi)); return r;
}
__device__ __forceinline__ void fma2(uint64_t& d, uint64_t a, uint64_t b) {
    asm("fma.rn.f32x2 %0, %1, %2, %0;" : "+l"(d) : "l"(a), "l"(b));
}
__device__ __forceinline__ void unpack2(uint64_t v, float& lo, float& hi) {
    asm("mov.b64 {%0, %1}, %2;" : "=f"(lo), "=f"(hi) : "l"(v));
}

// ---------------- tf32 mma.sync helpers (sm_80+ PTX; works on compute_103) --
__device__ __forceinline__ uint32_t f2tf32(float f) {
    uint32_t r; asm("cvt.rna.tf32.f32 %0, %1;" : "=r"(r) : "f"(f)); return r;
}
__device__ __forceinline__ void mma16n8k8(float* d, const uint32_t* a, const uint32_t* b) {
    asm volatile("mma.sync.aligned.m16n8k8.row.col.f32.tf32.tf32.f32 "
        "{%0,%1,%2,%3}, {%4,%5,%6,%7}, {%8,%9}, {%0,%1,%2,%3};"
        : "+f"(d[0]), "+f"(d[1]), "+f"(d[2]), "+f"(d[3])
        : "r"(a[0]), "r"(a[1]), "r"(a[2]), "r"(a[3]), "r"(b[0]), "r"(b[1]));
}

// ---------------- init: h0 -> buffer 0, reset barrier ----------------
__global__ void init_kernel(const float* __restrict__ h0) {
    int i = blockIdx.x * blockDim.x + threadIdx.x;
    if (i < BB * HH) g_h[0][i] = h0[i];
    if (i == 0) g_arrive = 0u;
}

// ---------------- embedding gather ----------------
__global__ void embed_kernel(const int* __restrict__ idx, const float* __restrict__ table) {
    long gid = (long)blockIdx.x * blockDim.x + threadIdx.x;
    const long total = (long)M_ROWS * 75;
    if (gid >= total) return;
    long r = gid / 75;
    int  e4 = (int)(gid % 75);
    int row = idx[r];
    ((float4*)g_out1)[r * 75 + e4] = ((const float4*)table)[(long)row * 75 + e4];
}

// ---------------- zx GEMM via mma.sync tf32: [65536,300]@[300,2048]+bias -----
// CTA tile 128x128, 8 warps each 64x32, BK=32 (K padded to 320 with zeros).
#define LDA 136   // smem row stride (8-bank shift -> conflict-free frag loads)
__global__ __launch_bounds__(256) void zx_gemm_tc(const float* __restrict__ Wx,
                                                  const float* __restrict__ bias) {
    __shared__ uint32_t As[32][LDA];   // [k][m] tf32 bits
    __shared__ uint32_t Bs[32][LDA];   // [k][n] tf32 bits

    const int tid  = threadIdx.x;
    const int wid  = tid >> 5;
    const int lane = tid & 31;
    const int gid  = lane >> 2;        // group id 0..7
    const int tig  = lane & 3;         // thread-in-group 0..3
    const int wm   = wid >> 2;         // 0..1  (64-row half)
    const int wn   = wid & 3;          // 0..3  (32-col quarter)
    const int bm = blockIdx.y * 128;
    const int bn = blockIdx.x * 128;

    float acc[4][4][4];                // [mtile][ntile][c]
#pragma unroll
    for (int i = 0; i < 4; i++)
#pragma unroll
        for (int j = 0; j < 4; j++)
#pragma unroll
            for (int c = 0; c < 4; c++) acc[i][j][c] = 0.f;

    for (int k0 = 0; k0 < 320; k0 += 32) {
        // A tile: rows bm..bm+127, k cols k0..k0+31 (zeros past 300)
        {
            int row = tid >> 1;
            int kh  = (tid & 1) * 16;
            const float* src = &g_out1[(size_t)(bm + row) * EE + k0 + kh];
#pragma unroll
            for (int q = 0; q < 4; q++) {
                int kc = k0 + kh + q * 4;
                float4 v = make_float4(0.f, 0.f, 0.f, 0.f);
                if (kc + 3 < EE) v = *(const float4*)(src + q * 4);
                else {
                    if (kc + 0 < EE) v.x = src[q * 4 + 0];
                    if (kc + 1 < EE) v.y = src[q * 4 + 1];
                    if (kc + 2 < EE) v.z = src[q * 4 + 2];
                    if (kc + 3 < EE) v.w = src[q * 4 + 3];
                }
                As[kh + q * 4 + 0][row] = f2tf32(v.x);
                As[kh + q * 4 + 1][row] = f2tf32(v.y);
                As[kh + q * 4 + 2][row] = f2tf32(v.z);
                As[kh + q * 4 + 3][row] = f2tf32(v.w);
            }
        }
        // B tile: k rows k0..k0+31, cols bn..bn+127 (coalesced)
        {
            int k  = tid >> 3;
            int nq = (tid & 7) * 16;
#pragma unroll
            for (int q = 0; q < 4; q++) {
                float4 v = make_float4(0.f, 0.f, 0.f, 0.f);
                if (k0 + k < EE) v = *(const float4*)&Wx[(size_t)(k0 + k) * G4 + bn + nq + q * 4];
                Bs[k][nq + q * 4 + 0] = f2tf32(v.x);
                Bs[k][nq + q * 4 + 1] = f2tf32(v.y);
                Bs[k][nq + q * 4 + 2] = f2tf32(v.z);
                Bs[k][nq + q * 4 + 3] = f2tf32(v.w);
            }
        }
        __syncthreads();

#pragma unroll
        for (int s = 0; s < 4; s++) {           // 4 k8 steps
            const int ks = s * 8;
            uint32_t af[4][4], bf[4][2];
#pragma unroll
            for (int mt = 0; mt < 4; mt++) {
                int mb = wm * 64 + mt * 16 + gid;
                af[mt][0] = As[ks + tig][mb];
                af[mt][1] = As[ks + tig][mb + 8];
                af[mt][2] = As[ks + tig + 4][mb];
                af[mt][3] = As[ks + tig + 4][mb + 8];
            }
#pragma unroll
            for (int nt = 0; nt < 4; nt++) {
                int nb = wn * 32 + nt * 8 + gid;
                bf[nt][0] = Bs[ks + tig][nb];
                bf[nt][1] = Bs[ks + tig + 4][nb];
            }
#pragma unroll
            for (int mt = 0; mt < 4; mt++)
#pragma unroll
                for (int nt = 0; nt < 4; nt++)
                    mma16n8k8(acc[mt][nt], af[mt], bf[nt]);
        }
        __syncthreads();
    }

    // epilogue: add bias, store float2 pairs
#pragma unroll
    for (int mt = 0; mt < 4; mt++) {
        int r0 = bm + wm * 64 + mt * 16 + gid;
#pragma unroll
        for (int nt = 0; nt < 4; nt++) {
            int ncol = bn + wn * 32 + nt * 8 + tig * 2;
            float2 bv = *(const float2*)&bias[ncol];
            float2 lo = make_float2(acc[mt][nt][0] + bv.x, acc[mt][nt][1] + bv.y);
            float2 hi = make_float2(acc[mt][nt][2] + bv.x, acc[mt][nt][3] + bv.y);
            *(float2*)&g_zx[(size_t)r0 * G4 + ncol] = lo;
            *(float2*)&g_zx[(size_t)(r0 + 8) * G4 + ncol] = hi;
        }
    }
}

// ---------------- conv1 (round-1 form), only t in [6,13] ----------------
__global__ __launch_bounds__(256) void conv1_kernel(const float* __restrict__ W1,
                                                    const float* __restrict__ b1) {
    int bb = blockIdx.x >> 1;
    int th = blockIdx.x & 1;
    __shared__ float xs[19][EE];
    int tid = threadIdx.x;
    for (int i = tid; i < 19 * EE; i += 256) {
        int rt = i / EE, e = i % EE;
        xs[rt][e] = g_out1[((long)(bb * TT) + 2 + rt) * EE + e];
    }
    __syncthreads();
    int m = tid;
    float acc[4] = {0.f, 0.f, 0.f, 0.f};
    for (int w = 0; w < 10; w++) {
        for (int e = 0; e < EE; e++) {
            float wv = W1[((w * EE) + e) * 256 + m];
#pragma unroll
            for (int q = 0; q < 4; q++) acc[q] += xs[th * 4 + q + w][e] * wv;
        }
    }
    float bm = b1[m];
#pragma unroll
    for (int q = 0; q < 4; q++) {
        float v = acc[q] + bm;
        v = v > 0.f ? v : 0.f;
        g_c1[(bb * 8 + th * 4 + q) * 256 + m] = v;
    }
}

// ---------------- conv2 at t=9 ----------------
__global__ __launch_bounds__(512) void conv2_kernel(const float* __restrict__ W2,
                                                    const float* __restrict__ b2) {
    int bb = blockIdx.x;
    __shared__ float cs[8 * 256];
    int tid = threadIdx.x;
    for (int i = tid; i < 2048; i += 512) cs[i] = g_c1[bb * 2048 + i];
    __syncthreads();
    int n = tid;
    float acc = 0.f;
    for (int i = 0; i < 2048; i++)
        acc += cs[i] * W2[(long)i * HH + n];
    float v = acc + b2[n];
    v = v > 0.f ? v : 0.f;
    g_c2[bb * HH + n] = v;
}

// ---------------- res9 add: out_res9 += conv2 ----------------
__global__ void res9_kernel(float* __restrict__ out_res9) {
    int i = blockIdx.x * blockDim.x + threadIdx.x;
    if (i < BB * HH) out_res9[i] += g_c2[i];
}

// ---------------- persistent masked LSTM ----------------
#define LC 128
#define HS_STRIDE 516

__device__ __forceinline__ float sigf(float x) { return 1.f / (1.f + __expf(-x)); }

__global__ __launch_bounds__(256, 1) void lstm_kernel(const float* __restrict__ Wh,
                                                      const float* __restrict__ c0,
                                                      const int* __restrict__ in_seq,
                                                      float* __restrict__ out_enc,
                                                      float* __restrict__ out_res9,
                                                      float* __restrict__ out_c) {
    extern __shared__ float smemf[];
    float* hs     = smemf;                         // 64 * 516
    float* whs    = hs + 64 * HS_STRIDE;           // [jj][k][g] = 8192
    float* red    = whs + 8192;                    // 4096
    float* hstage = red + 4096;                    // 256

    const int tid = threadIdx.x;
    const int bg = tid & 15;
    const int jj = (tid >> 4) & 3;
    const int ks = tid >> 6;                 // k-split group 0..3 (warp pair)
    const int lt = tid & 63;                 // lane within group
    const int b  = tid & 63;
    const int jc = tid >> 6;
    const int j0 = blockIdx.x * 4;
    const int col = j0 + jc;

    for (int f = tid; f < 16 * 512; f += 256) {
        int wjj = f >> 11;
        int k   = (f >> 2) & 511;
        int g   = f & 3;
        whs[f] = Wh[(long)k * G4 + j0 + wjj + g * 512];
    }

    float creg = c0[b * HH + col];
    __syncthreads();

    // initial prefetch (t=0)
    size_t zb = ((size_t)b * TT + 0) * G4 + col;
    float zr0 = __ldg(&g_zx[zb]);
    float zr1 = __ldg(&g_zx[zb + 512]);
    float zr2 = __ldg(&g_zx[zb + 1024]);
    float zr3 = __ldg(&g_zx[zb + 1536]);
    int   mreg = in_seq[b * TT + 0];

    for (int t = 0; t < TT; t++) {
        const float* hsrc = g_h[t & 1];
        float* hdst = g_h[(t & 1) ^ 1];

        // phase B: sectioned h-load — each ks group loads only its own k-quarter
        for (int i = lt; i < 2048; i += 64) {
            int b2 = i >> 5, j = i & 31;
            float4 v = __ldcg(((const float4*)hsrc) + b2 * 128 + ks * 32 + j);
            *(float4*)&hs[b2 * HS_STRIDE + ks * 128 + j * 4] = v;
        }
        asm volatile("bar.sync %0, 64;" :: "r"(1 + ks) : "memory");

        // phase C: packed-f32x2 MMA on own k-quarter
        uint64_t accp[4][2];
#pragma unroll
        for (int i = 0; i < 4; i++) { accp[i][0] = 0ull; accp[i][1] = 0ull; }

        const int kbase = ks * 128;
#pragma unroll 4
        for (int kk = 0; kk < 128; kk += 4) {
            const int k = kbase + kk;
            float4 hv[4];
#pragma unroll
            for (int i = 0; i < 4; i++)
                hv[i] = *(const float4*)&hs[(i * 16 + bg) * HS_STRIDE + k];
            const ulonglong2* wv2 = (const ulonglong2*)&whs[(jj * 512 + k) * 4];
#pragma unroll
            for (int q = 0; q < 4; q++) {
                ulonglong2 w = wv2[q];
#pragma unroll
                for (int i = 0; i < 4; i++) {
                    float hvq = ((const float*)&hv[i])[q];
                    uint64_t hb = pack2(hvq, hvq);
                    fma2(accp[i][0], hb, w.x);
                    fma2(accp[i][1], hb, w.y);
                }
            }
        }
#pragma unroll
        for (int i = 0; i < 4; i++) {
#pragma unroll
            for (int p = 0; p < 2; p++) {
                float v0, v1;
                unpack2(accp[i][p], v0, v1);
                int g = 2 * p;
                red[((ks * 4 + g) * 4 + jj) * 64 + i * 16 + bg] = v0;
                red[((ks * 4 + g + 1) * 4 + jj) * 64 + i * 16 + bg] = v1;
            }
        }
        __syncthreads();

        // phase D: one (b, col) per thread
        {
            float z0 = zr0, z1 = zr1, z2 = zr2, z3 = zr3;
#pragma unroll
            for (int r = 0; r < 4; r++) {
                z0 += red[((r * 4 + 0) * 4 + jc) * 64 + b];
                z1 += red[((r * 4 + 1) * 4 + jc) * 64 + b];
                z2 += red[((r * 4 + 2) * 4 + jc) * 64 + b];
                z3 += red[((r * 4 + 3) * 4 + jc) * 64 + b];
            }
            float cn = sigf(z1) * creg + sigf(z0) * tanhf(z2);
            float hn = sigf(z3) * tanhf(cn);
            if (mreg == 0) {
                hn = hs[b * HS_STRIDE + col];
                cn = creg;
            }
            creg = cn;
            hstage[b * 4 + jc] = hn;
            if (t == 9)      out_res9[b * HH + col] = hn;    // conv2 added later
            if (t == TT - 1) out_c[b * HH + col] = cn;
        }
        __syncthreads();

        // phase E: coalesced stores of new h + out_enc
        if (tid < 64) {
            float4 hv4 = *(const float4*)&hstage[tid * 4];
            __stcg((float4*)&hdst[tid * HH + j0], hv4);
            *(float4*)&out_enc[((size_t)tid * TT + t) * HH + j0] = hv4;
        }

        // prefetch t+1 (flies across the barrier)
        if (t + 1 < TT) {
            zb = ((size_t)b * TT + (t + 1)) * G4 + col;
            zr0 = __ldg(&g_zx[zb]);
            zr1 = __ldg(&g_zx[zb + 512]);
            zr2 = __ldg(&g_zx[zb + 1024]);
            zr3 = __ldg(&g_zx[zb + 1536]);
            mreg = in_seq[b * TT + t + 1];
        }

        // ---- grid barrier ----
        __threadfence();
        __syncthreads();
        if (tid == 0) {
            atomicAdd(&g_arrive, 1u);
            unsigned target = (unsigned)gridDim.x * (unsigned)(t + 1);
            while (*((volatile unsigned*)&g_arrive) < target) { }
        }
        __syncthreads();
    }
}

// ---------------- launch ----------------
extern "C" void kernel_launch(void* const* d_in, const int* in_sizes, int n_in,
                              void* d_out, int out_size) {
    const int*   in_seq = (const int*)  d_in[0];
    const float* h0     = (const float*)d_in[1];
    const float* c0     = (const float*)d_in[2];
    const float* table  = (const float*)d_in[3];
    const float* W1     = (const float*)d_in[4];
    const float* b1     = (const float*)d_in[5];
    const float* W2     = (const float*)d_in[6];
    const float* b2     = (const float*)d_in[7];
    const float* Wx     = (const float*)d_in[8];
    const float* Wh     = (const float*)d_in[9];
    const float* bias   = (const float*)d_in[10];

    float* out      = (float*)d_out;
    float* out_enc  = out;
    float* out_res9 = out + (size_t)BB * TT * HH;
    float* out_c    = out_res9 + BB * HH;

    const int lstm_smem = (64 * HS_STRIDE + 8192 + 4096 + 256) * 4;
    cudaFuncSetAttribute(lstm_kernel, cudaFuncAttributeMaxDynamicSharedMemorySize, lstm_smem);

    init_kernel<<<(BB * HH + 255) / 256, 256>>>(h0);
    embed_kernel<<<(int)(((long)M_ROWS * 75 + 255) / 256), 256>>>(in_seq, table);
    dim3 gg(G4 / 128, M_ROWS / 128);   // (16, 512)
    zx_gemm_tc<<<gg, 256>>>(Wx, bias);
    lstm_kernel<<<LC, 256, lstm_smem>>>(Wh, c0, in_seq, out_enc, out_res9, out_c);  // #4 -> profiled
    conv1_kernel<<<BB * 2, 256>>>(W1, b1);
    conv2_kernel<<<BB, 512>>>(W2, b2);
    res9_kernel<<<(BB * HH + 255) / 256, 256>>>(out_res9);
}

// round 8
// speedup vs baseline: 2.8111x; 1.3048x over previous
#include <cuda_runtime.h>
#include <cstdint>

#define BB 64
#define TT 1024
#define EE 300
#define HH 512
#define G4 2048
#define M_ROWS (BB*TT)

// ---------------- scratch (device globals; no allocations) ----------------
__device__ float g_out1[(size_t)M_ROWS * EE];     // embeddings
__device__ float g_zx[(size_t)M_ROWS * G4];       // zx = out1@Wx + b
__device__ float g_h[2][BB * HH];                 // double-buffered hidden state
__device__ float g_c1[BB * 8 * 256];              // conv1 window t=6..13
__device__ float g_c2[BB * HH];                   // conv2 at t=9
__device__ unsigned g_flags[128 * 32];            // per-CTA barrier flags (128B stride)

// ---------------- tf32 mma.sync helpers ----------------
__device__ __forceinline__ uint32_t f2tf32(float f) {
    uint32_t r; asm("cvt.rna.tf32.f32 %0, %1;" : "=r"(r) : "f"(f)); return r;
}
__device__ __forceinline__ void mma16n8k8(float* d, const uint32_t* a, const uint32_t* b) {
    asm volatile("mma.sync.aligned.m16n8k8.row.col.f32.tf32.tf32.f32 "
        "{%0,%1,%2,%3}, {%4,%5,%6,%7}, {%8,%9}, {%0,%1,%2,%3};"
        : "+f"(d[0]), "+f"(d[1]), "+f"(d[2]), "+f"(d[3])
        : "r"(a[0]), "r"(a[1]), "r"(a[2]), "r"(a[3]), "r"(b[0]), "r"(b[1]));
}

// ---------------- init: h0 -> buffer 0, reset flags ----------------
__global__ void init_kernel(const float* __restrict__ h0) {
    int i = blockIdx.x * blockDim.x + threadIdx.x;
    if (i < BB * HH) g_h[0][i] = h0[i];
    if (i < 128 * 32) g_flags[i] = 0u;
}

// ---------------- embedding gather ----------------
__global__ void embed_kernel(const int* __restrict__ idx, const float* __restrict__ table) {
    long gid = (long)blockIdx.x * blockDim.x + threadIdx.x;
    const long total = (long)M_ROWS * 75;
    if (gid >= total) return;
    long r = gid / 75;
    int  e4 = (int)(gid % 75);
    int row = idx[r];
    ((float4*)g_out1)[r * 75 + e4] = ((const float4*)table)[(long)row * 75 + e4];
}

// ---------------- zx GEMM via mma.sync tf32 (proven) -------------
#define LDA 136
__global__ __launch_bounds__(256) void zx_gemm_tc(const float* __restrict__ Wx,
                                                  const float* __restrict__ bias) {
    __shared__ uint32_t As[32][LDA];
    __shared__ uint32_t Bs[32][LDA];

    const int tid  = threadIdx.x;
    const int wid  = tid >> 5;
    const int lane = tid & 31;
    const int gid  = lane >> 2;
    const int tig  = lane & 3;
    const int wm   = wid >> 2;
    const int wn   = wid & 3;
    const int bm = blockIdx.y * 128;
    const int bn = blockIdx.x * 128;

    float acc[4][4][4];
#pragma unroll
    for (int i = 0; i < 4; i++)
#pragma unroll
        for (int j = 0; j < 4; j++)
#pragma unroll
            for (int c = 0; c < 4; c++) acc[i][j][c] = 0.f;

    for (int k0 = 0; k0 < 320; k0 += 32) {
        {
            int row = tid >> 1;
            int kh  = (tid & 1) * 16;
            const float* src = &g_out1[(size_t)(bm + row) * EE + k0 + kh];
#pragma unroll
            for (int q = 0; q < 4; q++) {
                int kc = k0 + kh + q * 4;
                float4 v = make_float4(0.f, 0.f, 0.f, 0.f);
                if (kc + 3 < EE) v = *(const float4*)(src + q * 4);
                else {
                    if (kc + 0 < EE) v.x = src[q * 4 + 0];
                    if (kc + 1 < EE) v.y = src[q * 4 + 1];
                    if (kc + 2 < EE) v.z = src[q * 4 + 2];
                    if (kc + 3 < EE) v.w = src[q * 4 + 3];
                }
                As[kh + q * 4 + 0][row] = f2tf32(v.x);
                As[kh + q * 4 + 1][row] = f2tf32(v.y);
                As[kh + q * 4 + 2][row] = f2tf32(v.z);
                As[kh + q * 4 + 3][row] = f2tf32(v.w);
            }
        }
        {
            int k  = tid >> 3;
            int nq = (tid & 7) * 16;
#pragma unroll
            for (int q = 0; q < 4; q++) {
                float4 v = make_float4(0.f, 0.f, 0.f, 0.f);
                if (k0 + k < EE) v = *(const float4*)&Wx[(size_t)(k0 + k) * G4 + bn + nq + q * 4];
                Bs[k][nq + q * 4 + 0] = f2tf32(v.x);
                Bs[k][nq + q * 4 + 1] = f2tf32(v.y);
                Bs[k][nq + q * 4 + 2] = f2tf32(v.z);
                Bs[k][nq + q * 4 + 3] = f2tf32(v.w);
            }
        }
        __syncthreads();

#pragma unroll
        for (int s = 0; s < 4; s++) {
            const int ks = s * 8;
            uint32_t af[4][4], bf[4][2];
#pragma unroll
            for (int mt = 0; mt < 4; mt++) {
                int mb = wm * 64 + mt * 16 + gid;
                af[mt][0] = As[ks + tig][mb];
                af[mt][1] = As[ks + tig][mb + 8];
                af[mt][2] = As[ks + tig + 4][mb];
                af[mt][3] = As[ks + tig + 4][mb + 8];
            }
#pragma unroll
            for (int nt = 0; nt < 4; nt++) {
                int nb = wn * 32 + nt * 8 + gid;
                bf[nt][0] = Bs[ks + tig][nb];
                bf[nt][1] = Bs[ks + tig + 4][nb];
            }
#pragma unroll
            for (int mt = 0; mt < 4; mt++)
#pragma unroll
                for (int nt = 0; nt < 4; nt++)
                    mma16n8k8(acc[mt][nt], af[mt], bf[nt]);
        }
        __syncthreads();
    }

#pragma unroll
    for (int mt = 0; mt < 4; mt++) {
        int r0 = bm + wm * 64 + mt * 16 + gid;
#pragma unroll
        for (int nt = 0; nt < 4; nt++) {
            int ncol = bn + wn * 32 + nt * 8 + tig * 2;
            float2 bv = *(const float2*)&bias[ncol];
            float2 lo = make_float2(acc[mt][nt][0] + bv.x, acc[mt][nt][1] + bv.y);
            float2 hi = make_float2(acc[mt][nt][2] + bv.x, acc[mt][nt][3] + bv.y);
            *(float2*)&g_zx[(size_t)r0 * G4 + ncol] = lo;
            *(float2*)&g_zx[(size_t)(r0 + 8) * G4 + ncol] = hi;
        }
    }
}

// ---------------- conv1 ----------------
__global__ __launch_bounds__(256) void conv1_kernel(const float* __restrict__ W1,
                                                    const float* __restrict__ b1) {
    int bb = blockIdx.x >> 1;
    int th = blockIdx.x & 1;
    __shared__ float xs[19][EE];
    int tid = threadIdx.x;
    for (int i = tid; i < 19 * EE; i += 256) {
        int rt = i / EE, e = i % EE;
        xs[rt][e] = g_out1[((long)(bb * TT) + 2 + rt) * EE + e];
    }
    __syncthreads();
    int m = tid;
    float acc[4] = {0.f, 0.f, 0.f, 0.f};
    for (int w = 0; w < 10; w++) {
        for (int e = 0; e < EE; e++) {
            float wv = W1[((w * EE) + e) * 256 + m];
#pragma unroll
            for (int q = 0; q < 4; q++) acc[q] += xs[th * 4 + q + w][e] * wv;
        }
    }
    float bm = b1[m];
#pragma unroll
    for (int q = 0; q < 4; q++) {
        float v = acc[q] + bm;
        v = v > 0.f ? v : 0.f;
        g_c1[(bb * 8 + th * 4 + q) * 256 + m] = v;
    }
}

// ---------------- conv2 at t=9 ----------------
__global__ __launch_bounds__(512) void conv2_kernel(const float* __restrict__ W2,
                                                    const float* __restrict__ b2) {
    int bb = blockIdx.x;
    __shared__ float cs[8 * 256];
    int tid = threadIdx.x;
    for (int i = tid; i < 2048; i += 512) cs[i] = g_c1[bb * 2048 + i];
    __syncthreads();
    int n = tid;
    float acc = 0.f;
    for (int i = 0; i < 2048; i++)
        acc += cs[i] * W2[(long)i * HH + n];
    float v = acc + b2[n];
    v = v > 0.f ? v : 0.f;
    g_c2[bb * HH + n] = v;
}

// ---------------- res9 add ----------------
__global__ void res9_kernel(float* __restrict__ out_res9) {
    int i = blockIdx.x * blockDim.x + threadIdx.x;
    if (i < BB * HH) out_res9[i] += g_c2[i];
}

// ---------------- persistent masked LSTM (tensor-core recurrence) ----------
// Per CTA: z-tile = 64 batch x 16 cols (4 h-cols x 4 gates), K = 512.
// 8 warps = (mt 0..3) x (nt 0..1); each warp: m16n8, full K, Wh frags in regs.
#define LC 128
#define FR_KS 132                        // uint32 stride per kstep (128 + 4 pad)
#define FR_MT (64 * FR_KS)               // per M-tile

__device__ __forceinline__ float sigf(float x) { return 1.f / (1.f + __expf(-x)); }

__global__ __launch_bounds__(256, 1) void lstm_kernel(const float* __restrict__ Wh,
                                                      const float* __restrict__ c0,
                                                      const float* __restrict__ h0,
                                                      const int* __restrict__ in_seq,
                                                      float* __restrict__ out_enc,
                                                      float* __restrict__ out_res9,
                                                      float* __restrict__ out_c) {
    extern __shared__ uint32_t smemu[];
    uint32_t* frag   = smemu;                        // 4 * 64 * 132 = 33792 u32
    float*    red    = (float*)(frag + 4 * FR_MT);   // 16 * 66
    float*    hstage = red + 16 * 66;                // 256

    const int tid  = threadIdx.x;
    const int warp = tid >> 5;
    const int lane = tid & 31;
    const int gid  = lane >> 2;
    const int tig  = lane & 3;
    const int mt   = warp >> 1;
    const int nt   = warp & 1;
    const int b    = tid & 63;
    const int jc   = tid >> 6;
    const int j0   = blockIdx.x * 4;
    const int col  = j0 + jc;

    // ---- Wh fragments -> registers (loop-invariant), col c = g*4 + jj ----
    uint32_t bfr[64][2];
    {
        int c  = nt * 8 + gid;
        int g  = c >> 2, jj = c & 3;
        int wcol = j0 + jj + g * 512;
#pragma unroll 64
        for (int ks = 0; ks < 64; ks++) {
            bfr[ks][0] = f2tf32(Wh[(size_t)(ks * 8 + tig) * G4 + wcol]);
            bfr[ks][1] = f2tf32(Wh[(size_t)(ks * 8 + tig + 4) * G4 + wcol]);
        }
    }

    float creg = c0[b * HH + col];
    hstage[b * 4 + jc] = h0[b * HH + col];
    __syncthreads();

    // initial zx/mask prefetch (t=0)
    size_t zb = ((size_t)b * TT) * G4 + col;
    float zr0 = __ldg(&g_zx[zb]);
    float zr1 = __ldg(&g_zx[zb + 512]);
    float zr2 = __ldg(&g_zx[zb + 1024]);
    float zr3 = __ldg(&g_zx[zb + 1536]);
    int   mreg = in_seq[b * TT];

    for (int t = 0; t < TT; t++) {
        const float* hsrc = g_h[t & 1];
        float* hdst = g_h[(t & 1) ^ 1];

        // ---- stage h -> tf32 fragment-major SMEM ----
#pragma unroll 1
        for (int base2 = 0; base2 < 4; base2++) {
            float4 v[8];
#pragma unroll
            for (int u = 0; u < 8; u++)
                v[u] = __ldcg((const float4*)hsrc + (base2 * 8 + u) * 256 + tid);
#pragma unroll
            for (int u = 0; u < 8; u++) {
                int i  = (base2 * 8 + u) * 256 + tid;
                int bb = i >> 7;                 // batch row (128 float4/row)
                int k0 = (i & 127) * 4;
                int mtv = bb >> 4, r = bb & 15, g2 = r & 7, hi = r >> 3;
                int ks = k0 >> 3, khi = (k0 >> 2) & 1, slot = khi * 2 + hi;
                uint32_t* du = &frag[(mtv * 64 + ks) * FR_KS + g2 * 16 + slot];
                du[0]  = f2tf32(v[u].x);
                du[4]  = f2tf32(v[u].y);
                du[8]  = f2tf32(v[u].z);
                du[12] = f2tf32(v[u].w);
            }
        }
        __syncthreads();

        // ---- MMA: full K per warp, Wh from registers ----
        float acc[4] = {0.f, 0.f, 0.f, 0.f};
        const uint32_t* fb = frag + mt * FR_MT + lane * 4;
#pragma unroll 64
        for (int ks = 0; ks < 64; ks++) {
            uint32_t af[4];
            *(uint4*)af = *(const uint4*)(fb + ks * FR_KS);
            mma16n8k8(acc, af, bfr[ks]);
        }

        // ---- funnel acc -> red[c][b] ----
        {
            int c0i = nt * 8 + tig * 2;
            int r0  = mt * 16 + gid;
            red[(c0i    ) * 66 + r0]     = acc[0];
            red[(c0i + 1) * 66 + r0]     = acc[1];
            red[(c0i    ) * 66 + r0 + 8] = acc[2];
            red[(c0i + 1) * 66 + r0 + 8] = acc[3];
        }
        __syncthreads();

        // ---- gates: one (b, col) per thread ----
        {
            float z0 = zr0 + red[(0 * 4 + jc) * 66 + b];
            float z1 = zr1 + red[(1 * 4 + jc) * 66 + b];
            float z2 = zr2 + red[(2 * 4 + jc) * 66 + b];
            float z3 = zr3 + red[(3 * 4 + jc) * 66 + b];
            float cn = sigf(z1) * creg + sigf(z0) * tanhf(z2);
            float hn = sigf(z3) * tanhf(cn);
            if (mreg == 0) {                  // masked: carry state
                hn = hstage[b * 4 + jc];      // own slot, no race
                cn = creg;
            }
            creg = cn;
            hstage[b * 4 + jc] = hn;
            if (t == 9)      out_res9[b * HH + col] = hn;
            if (t == TT - 1) out_c[b * HH + col] = cn;
        }
        __syncthreads();

        // ---- coalesced h + out_enc stores ----
        if (tid < 64) {
            float4 hv4 = *(const float4*)&hstage[tid * 4];
            __stcg((float4*)&hdst[tid * HH + j0], hv4);
            *(float4*)&out_enc[((size_t)tid * TT + t) * HH + j0] = hv4;
        }

        // ---- prefetch t+1 (flies across barrier) ----
        if (t + 1 < TT) {
            zb = ((size_t)b * TT + (t + 1)) * G4 + col;
            zr0 = __ldg(&g_zx[zb]);
            zr1 = __ldg(&g_zx[zb + 512]);
            zr2 = __ldg(&g_zx[zb + 1024]);
            zr3 = __ldg(&g_zx[zb + 1536]);
            mreg = in_seq[b * TT + t + 1];
        }

        // ---- grid barrier: distributed flags (VOLATILE poll — no hoisting) ----
        __threadfence();
        __syncthreads();
        if (tid == 0) __stcg(&g_flags[blockIdx.x * 32], (unsigned)(t + 1));
        if (warp == 0) {
            const unsigned tgt = (unsigned)(t + 1);
            volatile unsigned* vf = g_flags;
            bool ok;
            do {
                unsigned v0 = vf[lane * 32];
                unsigned v1 = vf[(lane + 32) * 32];
                unsigned v2 = vf[(lane + 64) * 32];
                unsigned v3 = vf[(lane + 96) * 32];
                ok = (v0 >= tgt) && (v1 >= tgt) && (v2 >= tgt) && (v3 >= tgt);
            } while (!__all_sync(0xffffffffu, ok));
        }
        __syncthreads();
    }
}

// ---------------- launch ----------------
extern "C" void kernel_launch(void* const* d_in, const int* in_sizes, int n_in,
                              void* d_out, int out_size) {
    const int*   in_seq = (const int*)  d_in[0];
    const float* h0     = (const float*)d_in[1];
    const float* c0     = (const float*)d_in[2];
    const float* table  = (const float*)d_in[3];
    const float* W1     = (const float*)d_in[4];
    const float* b1     = (const float*)d_in[5];
    const float* W2     = (const float*)d_in[6];
    const float* b2     = (const float*)d_in[7];
    const float* Wx     = (const float*)d_in[8];
    const float* Wh     = (const float*)d_in[9];
    const float* bias   = (const float*)d_in[10];

    float* out      = (float*)d_out;
    float* out_enc  = out;
    float* out_res9 = out + (size_t)BB * TT * HH;
    float* out_c    = out_res9 + BB * HH;

    const int lstm_smem = (4 * FR_MT + 16 * 66 + 256) * 4;   // ~140.4 KB
    cudaFuncSetAttribute(lstm_kernel, cudaFuncAttributeMaxDynamicSharedMemorySize, lstm_smem);

    init_kernel<<<(BB * HH + 255) / 256, 256>>>(h0);
    embed_kernel<<<(int)(((long)M_ROWS * 75 + 255) / 256), 256>>>(in_seq, table);
    dim3 gg(G4 / 128, M_ROWS / 128);
    zx_gemm_tc<<<gg, 256>>>(Wx, bias);
    lstm_kernel<<<LC, 256, lstm_smem>>>(Wh, c0, h0, in_seq, out_enc, out_res9, out_c);  // #4 -> profiled
    conv1_kernel<<<BB * 2, 256>>>(W1, b1);
    conv2_kernel<<<BB, 512>>>(W2, b2);
    res9_kernel<<<(BB * HH + 255) / 256, 256>>>(out_res9);
}

// round 9
// speedup vs baseline: 2.8441x; 1.0117x over previous
#include <cuda_runtime.h>
#include <cstdint>

#define BB 64
#define TT 1024
#define EE 300
#define HH 512
#define G4 2048
#define M_ROWS (BB*TT)

// ---------------- scratch (device globals; no allocations) ----------------
__device__ float    g_out1[(size_t)M_ROWS * EE];   // embeddings
__device__ float    g_zx[(size_t)M_ROWS * G4];     // zx = out1@Wx + b
__device__ uint32_t g_htf[2][32768];               // h in tf32, fragment-major, dbl-buf
__device__ float    g_c1[BB * 8 * 256];            // conv1 window t=6..13
__device__ float    g_c2[BB * HH];                 // conv2 at t=9
__device__ unsigned g_flags[128 * 32];             // per-CTA barrier flags (128B stride)

// ---------------- tf32 mma.sync helpers ----------------
__device__ __forceinline__ uint32_t f2tf32(float f) {
    uint32_t r; asm("cvt.rna.tf32.f32 %0, %1;" : "=r"(r) : "f"(f)); return r;
}
__device__ __forceinline__ void mma16n8k8(float* d, const uint32_t* a, const uint32_t* b) {
    asm volatile("mma.sync.aligned.m16n8k8.row.col.f32.tf32.tf32.f32 "
        "{%0,%1,%2,%3}, {%4,%5,%6,%7}, {%8,%9}, {%0,%1,%2,%3};"
        : "+f"(d[0]), "+f"(d[1]), "+f"(d[2]), "+f"(d[3])
        : "r"(a[0]), "r"(a[1]), "r"(a[2]), "r"(a[3]), "r"(b[0]), "r"(b[1]));
}

// fragment-layout index for h value (b, col)
__device__ __forceinline__ int htf_idx(int b, int col) {
    int mtv = b >> 4, g2 = b & 7, hi = (b >> 3) & 1;
    int ks = col >> 3, khi = (col >> 2) & 1, kq = col & 3;
    int slot = khi * 2 + hi;
    return (((mtv * 64 + ks) << 7) + (g2 << 4) + (kq << 2) + slot);
}

// ---------------- init: h0 -> g_htf[0] (frag layout), reset flags ----------
__global__ void init_kernel(const float* __restrict__ h0) {
    int i = blockIdx.x * blockDim.x + threadIdx.x;
    if (i < BB * HH) {
        int b = i >> 9, col = i & 511;
        g_htf[0][htf_idx(b, col)] = f2tf32(h0[i]);
    }
    if (i < 128 * 32) g_flags[i] = 0u;
}

// ---------------- embedding gather ----------------
__global__ void embed_kernel(const int* __restrict__ idx, const float* __restrict__ table) {
    long gid = (long)blockIdx.x * blockDim.x + threadIdx.x;
    const long total = (long)M_ROWS * 75;
    if (gid >= total) return;
    long r = gid / 75;
    int  e4 = (int)(gid % 75);
    int row = idx[r];
    ((float4*)g_out1)[r * 75 + e4] = ((const float4*)table)[(long)row * 75 + e4];
}

// ---------------- zx GEMM via mma.sync tf32 (proven) -------------
#define LDA 136
__global__ __launch_bounds__(256) void zx_gemm_tc(const float* __restrict__ Wx,
                                                  const float* __restrict__ bias) {
    __shared__ uint32_t As[32][LDA];
    __shared__ uint32_t Bs[32][LDA];

    const int tid  = threadIdx.x;
    const int wid  = tid >> 5;
    const int lane = tid & 31;
    const int gid  = lane >> 2;
    const int tig  = lane & 3;
    const int wm   = wid >> 2;
    const int wn   = wid & 3;
    const int bm = blockIdx.y * 128;
    const int bn = blockIdx.x * 128;

    float acc[4][4][4];
#pragma unroll
    for (int i = 0; i < 4; i++)
#pragma unroll
        for (int j = 0; j < 4; j++)
#pragma unroll
            for (int c = 0; c < 4; c++) acc[i][j][c] = 0.f;

    for (int k0 = 0; k0 < 320; k0 += 32) {
        {
            int row = tid >> 1;
            int kh  = (tid & 1) * 16;
            const float* src = &g_out1[(size_t)(bm + row) * EE + k0 + kh];
#pragma unroll
            for (int q = 0; q < 4; q++) {
                int kc = k0 + kh + q * 4;
                float4 v = make_float4(0.f, 0.f, 0.f, 0.f);
                if (kc + 3 < EE) v = *(const float4*)(src + q * 4);
                else {
                    if (kc + 0 < EE) v.x = src[q * 4 + 0];
                    if (kc + 1 < EE) v.y = src[q * 4 + 1];
                    if (kc + 2 < EE) v.z = src[q * 4 + 2];
                    if (kc + 3 < EE) v.w = src[q * 4 + 3];
                }
                As[kh + q * 4 + 0][row] = f2tf32(v.x);
                As[kh + q * 4 + 1][row] = f2tf32(v.y);
                As[kh + q * 4 + 2][row] = f2tf32(v.z);
                As[kh + q * 4 + 3][row] = f2tf32(v.w);
            }
        }
        {
            int k  = tid >> 3;
            int nq = (tid & 7) * 16;
#pragma unroll
            for (int q = 0; q < 4; q++) {
                float4 v = make_float4(0.f, 0.f, 0.f, 0.f);
                if (k0 + k < EE) v = *(const float4*)&Wx[(size_t)(k0 + k) * G4 + bn + nq + q * 4];
                Bs[k][nq + q * 4 + 0] = f2tf32(v.x);
                Bs[k][nq + q * 4 + 1] = f2tf32(v.y);
                Bs[k][nq + q * 4 + 2] = f2tf32(v.z);
                Bs[k][nq + q * 4 + 3] = f2tf32(v.w);
            }
        }
        __syncthreads();

#pragma unroll
        for (int s = 0; s < 4; s++) {
            const int ks = s * 8;
            uint32_t af[4][4], bf[4][2];
#pragma unroll
            for (int mt = 0; mt < 4; mt++) {
                int mb = wm * 64 + mt * 16 + gid;
                af[mt][0] = As[ks + tig][mb];
                af[mt][1] = As[ks + tig][mb + 8];
                af[mt][2] = As[ks + tig + 4][mb];
                af[mt][3] = As[ks + tig + 4][mb + 8];
            }
#pragma unroll
            for (int nt = 0; nt < 4; nt++) {
                int nb = wn * 32 + nt * 8 + gid;
                bf[nt][0] = Bs[ks + tig][nb];
                bf[nt][1] = Bs[ks + tig + 4][nb];
            }
#pragma unroll
            for (int mt = 0; mt < 4; mt++)
#pragma unroll
                for (int nt = 0; nt < 4; nt++)
                    mma16n8k8(acc[mt][nt], af[mt], bf[nt]);
        }
        __syncthreads();
    }

#pragma unroll
    for (int mt = 0; mt < 4; mt++) {
        int r0 = bm + wm * 64 + mt * 16 + gid;
#pragma unroll
        for (int nt = 0; nt < 4; nt++) {
            int ncol = bn + wn * 32 + nt * 8 + tig * 2;
            float2 bv = *(const float2*)&bias[ncol];
            float2 lo = make_float2(acc[mt][nt][0] + bv.x, acc[mt][nt][1] + bv.y);
            float2 hi = make_float2(acc[mt][nt][2] + bv.x, acc[mt][nt][3] + bv.y);
            *(float2*)&g_zx[(size_t)r0 * G4 + ncol] = lo;
            *(float2*)&g_zx[(size_t)(r0 + 8) * G4 + ncol] = hi;
        }
    }
}

// ---------------- conv1: 512 CTAs, one output t per CTA ----------------
__global__ __launch_bounds__(256) void conv1_kernel(const float* __restrict__ W1,
                                                    const float* __restrict__ b1) {
    int bb = blockIdx.x >> 3;
    int th = blockIdx.x & 7;          // output t = 6 + th; inputs rows 2+th .. 11+th
    __shared__ float xs[10 * EE];
    int tid = threadIdx.x;
    for (int i = tid; i < 10 * EE; i += 256) {
        int rt = i / EE, e = i % EE;
        xs[rt * EE + e] = g_out1[((long)(bb * TT) + 2 + th + rt) * EE + e];
    }
    __syncthreads();
    int m = tid;
    float acc = 0.f;
#pragma unroll 5
    for (int i = 0; i < 10 * EE; i++)
        acc += xs[i] * W1[(size_t)i * 256 + m];
    float v = acc + b1[m];
    v = v > 0.f ? v : 0.f;
    g_c1[(bb * 8 + th) * 256 + m] = v;
}

// ---------------- conv2 at t=9 ----------------
__global__ __launch_bounds__(512) void conv2_kernel(const float* __restrict__ W2,
                                                    const float* __restrict__ b2) {
    int bb = blockIdx.x;
    __shared__ float cs[8 * 256];
    int tid = threadIdx.x;
    for (int i = tid; i < 2048; i += 512) cs[i] = g_c1[bb * 2048 + i];
    __syncthreads();
    int n = tid;
    float acc = 0.f;
#pragma unroll 4
    for (int i = 0; i < 2048; i++)
        acc += cs[i] * W2[(size_t)i * HH + n];
    float v = acc + b2[n];
    v = v > 0.f ? v : 0.f;
    g_c2[bb * HH + n] = v;
}

// ---------------- res9 add ----------------
__global__ void res9_kernel(float* __restrict__ out_res9) {
    int i = blockIdx.x * blockDim.x + threadIdx.x;
    if (i < BB * HH) out_res9[i] += g_c2[i];
}

// ---------------- persistent masked LSTM (tensor-core recurrence) ----------
// h lives in GLOBAL memory pre-converted to tf32 in fragment-major layout:
// [mtv(4)][ks(64)][g2(8)][kq(4)][slot(4)] — consumer staging is a pure copy.
#define LC 128

__device__ __forceinline__ float sigf(float x) { return 1.f / (1.f + __expf(-x)); }

__global__ __launch_bounds__(256, 1) void lstm_kernel(const float* __restrict__ Wh,
                                                      const float* __restrict__ c0,
                                                      const float* __restrict__ h0,
                                                      const int* __restrict__ in_seq,
                                                      float* __restrict__ out_enc,
                                                      float* __restrict__ out_res9,
                                                      float* __restrict__ out_c) {
    extern __shared__ uint32_t smemu[];
    uint32_t* frag   = smemu;                        // 32768 u32 (4 mt x 8192)
    float*    red    = (float*)(frag + 32768);       // 16 * 66
    float*    hstage = red + 16 * 66;                // 256

    const int tid  = threadIdx.x;
    const int warp = tid >> 5;
    const int lane = tid & 31;
    const int gid  = lane >> 2;
    const int tig  = lane & 3;
    const int mt   = warp >> 1;
    const int nt   = warp & 1;
    const int lt   = nt * 32 + lane;        // 0..63 within mt warp-pair
    const int b    = tid & 63;
    const int jc   = tid >> 6;
    const int j0   = blockIdx.x * 4;
    const int col  = j0 + jc;
    const int my_idx = htf_idx(b, col);     // this thread's slot in frag layout

    // ---- Wh fragments -> registers (loop-invariant), col c = g*4 + jj ----
    uint32_t bfr[64][2];
    {
        int c  = nt * 8 + gid;
        int g  = c >> 2, jj = c & 3;
        int wcol = j0 + jj + g * 512;
#pragma unroll 64
        for (int ks = 0; ks < 64; ks++) {
            bfr[ks][0] = f2tf32(Wh[(size_t)(ks * 8 + tig) * G4 + wcol]);
            bfr[ks][1] = f2tf32(Wh[(size_t)(ks * 8 + tig + 4) * G4 + wcol]);
        }
    }

    float creg = c0[b * HH + col];
    hstage[b * 4 + jc] = h0[b * HH + col];
    __syncthreads();

    // initial zx/mask prefetch (t=0)
    size_t zb = ((size_t)b * TT) * G4 + col;
    float zr0 = __ldg(&g_zx[zb]);
    float zr1 = __ldg(&g_zx[zb + 512]);
    float zr2 = __ldg(&g_zx[zb + 1024]);
    float zr3 = __ldg(&g_zx[zb + 1536]);
    int   mreg = in_seq[b * TT];

    for (int t = 0; t < TT; t++) {
        const uint4* hsrc = (const uint4*)g_htf[t & 1];
        uint32_t*    hdst = g_htf[(t & 1) ^ 1];

        // ---- stage own mt quarter: pure contiguous copy (2048 uint4/quarter) ----
        {
            const uint4* src = hsrc + mt * 2048;
            uint4* dst = (uint4*)(frag + mt * 8192);
#pragma unroll 8
            for (int j = lt; j < 2048; j += 64)
                dst[j] = __ldcg(src + j);
        }
        asm volatile("bar.sync %0, 64;" :: "r"(4 + mt) : "memory");

        // ---- MMA: full K per warp, Wh from registers ----
        float acc[4] = {0.f, 0.f, 0.f, 0.f};
        const uint32_t* fb = frag + mt * 8192 + lane * 4;
#pragma unroll 64
        for (int ks = 0; ks < 64; ks++) {
            uint32_t af[4];
            *(uint4*)af = *(const uint4*)(fb + ks * 128);
            mma16n8k8(acc, af, bfr[ks]);
        }

        // ---- funnel acc -> red[c][b] ----
        {
            int c0i = nt * 8 + tig * 2;
            int r0  = mt * 16 + gid;
            red[(c0i    ) * 66 + r0]     = acc[0];
            red[(c0i + 1) * 66 + r0]     = acc[1];
            red[(c0i    ) * 66 + r0 + 8] = acc[2];
            red[(c0i + 1) * 66 + r0 + 8] = acc[3];
        }
        __syncthreads();

        // ---- gates: one (b, col) per thread; producer-side tf32 h store ----
        {
            float z0 = zr0 + red[(0 * 4 + jc) * 66 + b];
            float z1 = zr1 + red[(1 * 4 + jc) * 66 + b];
            float z2 = zr2 + red[(2 * 4 + jc) * 66 + b];
            float z3 = zr3 + red[(3 * 4 + jc) * 66 + b];
            float cn = sigf(z1) * creg + sigf(z0) * tanhf(z2);
            float hn = sigf(z3) * tanhf(cn);
            if (mreg == 0) {                  // masked: carry state
                hn = hstage[b * 4 + jc];
                cn = creg;
            }
            creg = cn;
            hstage[b * 4 + jc] = hn;
            __stcg(&hdst[my_idx], f2tf32(hn));     // next-step h, frag layout
            if (t == 9)      out_res9[b * HH + col] = hn;
            if (t == TT - 1) out_c[b * HH + col] = cn;
        }
        __syncthreads();

        // ---- coalesced out_enc store ----
        if (tid < 64) {
            float4 hv4 = *(const float4*)&hstage[tid * 4];
            *(float4*)&out_enc[((size_t)tid * TT + t) * HH + j0] = hv4;
        }

        // ---- prefetch t+1 (flies across barrier) ----
        if (t + 1 < TT) {
            zb = ((size_t)b * TT + (t + 1)) * G4 + col;
            zr0 = __ldg(&g_zx[zb]);
            zr1 = __ldg(&g_zx[zb + 512]);
            zr2 = __ldg(&g_zx[zb + 1024]);
            zr3 = __ldg(&g_zx[zb + 1536]);
            mreg = in_seq[b * TT + t + 1];
        }

        // ---- grid barrier: release-store flag, volatile poll, acquire fence ----
        __syncthreads();
        if (tid == 0) {
            unsigned v = (unsigned)(t + 1);
            asm volatile("st.release.gpu.global.u32 [%0], %1;"
                         :: "l"(&g_flags[blockIdx.x * 32]), "r"(v) : "memory");
        }
        if (warp == 0) {
            const unsigned tgt = (unsigned)(t + 1);
            volatile unsigned* vf = g_flags;
            bool ok;
            do {
                unsigned v0 = vf[lane * 32];
                unsigned v1 = vf[(lane + 32) * 32];
                unsigned v2 = vf[(lane + 64) * 32];
                unsigned v3 = vf[(lane + 96) * 32];
                ok = (v0 >= tgt) && (v1 >= tgt) && (v2 >= tgt) && (v3 >= tgt);
            } while (!__all_sync(0xffffffffu, ok));
            asm volatile("fence.acq_rel.gpu;" ::: "memory");
        }
        __syncthreads();
    }
}

// ---------------- launch ----------------
extern "C" void kernel_launch(void* const* d_in, const int* in_sizes, int n_in,
                              void* d_out, int out_size) {
    const int*   in_seq = (const int*)  d_in[0];
    const float* h0     = (const float*)d_in[1];
    const float* c0     = (const float*)d_in[2];
    const float* table  = (const float*)d_in[3];
    const float* W1     = (const float*)d_in[4];
    const float* b1     = (const float*)d_in[5];
    const float* W2     = (const float*)d_in[6];
    const float* b2     = (const float*)d_in[7];
    const float* Wx     = (const float*)d_in[8];
    const float* Wh     = (const float*)d_in[9];
    const float* bias   = (const float*)d_in[10];

    float* out      = (float*)d_out;
    float* out_enc  = out;
    float* out_res9 = out + (size_t)BB * TT * HH;
    float* out_c    = out_res9 + BB * HH;

    const int lstm_smem = (32768 + 16 * 66 + 256) * 4;   // ~136.3 KB
    cudaFuncSetAttribute(lstm_kernel, cudaFuncAttributeMaxDynamicSharedMemorySize, lstm_smem);

    init_kernel<<<(BB * HH + 255) / 256, 256>>>(h0);
    embed_kernel<<<(int)(((long)M_ROWS * 75 + 255) / 256), 256>>>(in_seq, table);
    dim3 gg(G4 / 128, M_ROWS / 128);
    zx_gemm_tc<<<gg, 256>>>(Wx, bias);
    lstm_kernel<<<LC, 256, lstm_smem>>>(Wh, c0, h0, in_seq, out_enc, out_res9, out_c);  // #4 -> profiled
    conv1_kernel<<<BB * 8, 256>>>(W1, b1);
    conv2_kernel<<<BB, 512>>>(W2, b2);
    res9_kernel<<<(BB * HH + 255) / 256, 256>>>(out_res9);
}